// round 6
// baseline (speedup 1.0000x reference)
#include <cuda_runtime.h>
#include <cstdint>

#define HW      49
#define CDIM    256
#define NTHR    256
#define NB      2              // batches per CTA
#define GRID    1024
#define NCHUNK  16             // 16 channels per chunk
#define BUFW    4096           // words per buffer: 2 batches * 2048
#define WM_OFF  8192           // combined mask (float), 2401 (pad 2432)
#define SN_OFF  (WM_OFF + 2432)
#define DYN_WORDS (SN_OFF + 256)
#define NPAIR   1568           // channel-pairs per chunk (2b*2t*8kp*49)
#define NSLOT   13             // staging slots per staging thread (128 stagers)

// pack two fp32 -> bf16x2: lower 16 = even channel, upper 16 = odd channel
__device__ __forceinline__ uint32_t bf16pack(float even, float odd) {
    uint32_t r;
    asm("cvt.rn.bf16x2.f32 %0, %1, %2;" : "=r"(r) : "f"(odd), "f"(even));
    return r;
}
__device__ __forceinline__ void mma16(float* d, const uint32_t* a,
                                      uint32_t b0, uint32_t b1) {
    asm("mma.sync.aligned.m16n8k16.row.col.f32.bf16.bf16.f32 "
        "{%0,%1,%2,%3}, {%4,%5,%6,%7}, {%8,%9}, {%0,%1,%2,%3};"
        : "+f"(d[0]), "+f"(d[1]), "+f"(d[2]), "+f"(d[3])
        : "r"(a[0]), "r"(a[1]), "r"(a[2]), "r"(a[3]), "r"(b0), "r"(b1));
}

__global__ __launch_bounds__(NTHR, 2) void pixpro_ws(
    const float* __restrict__ baseF,   // [B, 256, 49]
    const float* __restrict__ momF,    // [B, 256, 49]
    const int*   __restrict__ baseA,   // [49*49] (p*49+q)
    const int*   __restrict__ momA,    // [49*49]
    float*       __restrict__ out)     // [B]
{
    extern __shared__ float sm[];
    uint32_t* smw = (uint32_t*)sm;
    __shared__ float wsum[4];

    const int tid  = threadIdx.x;
    const int wid  = tid >> 5;
    const int lane = tid & 31;
    const int tg   = lane & 3;
    const int gq   = lane >> 2;
    const int b0   = blockIdx.x * NB;
    const bool isMMA = wid < 4;

    // ---- init mask + norm accumulators ----
    for (int i = tid; i < HW * HW; i += NTHR) {
        int p = i / HW, q = i - p * HW;
        sm[WM_OFF + i] = (float)((baseA[i] == 1) + (momA[q * HW + p] == 1));
    }
    sm[SN_OFF + tid] = 0.f;

    // ---- staging state: packed descriptors (bb<<24 | t<<16 | kp<<8 | pos) ----
    uint32_t pk[NSLOT];
    float accn[NSLOT];
    const int t2 = tid & 127;
    if (!isMMA) {
        #pragma unroll
        for (int j = 0; j < NSLOT; ++j) {
            accn[j] = 0.f;
            int e = t2 + j * 128;
            if (e < NPAIR) {
                int bb = e / 784;
                int r  = e - bb * 784;
                int t  = r / 392;
                int s  = r - t * 392;
                int kp = s / 49;
                int pos = s - kp * 49;
                pk[j] = (uint32_t)((bb << 24) | (t << 16) | (kp << 8) | pos);
            }
        }
    }

    // stage chunk cc into buffer cc&1 (staging warps only)
    auto stage = [&](int cc) {
        uint32_t* dbuf = smw + (cc & 1) * BUFW;
        const int coff = cc * 784;
        #pragma unroll
        for (int j = 0; j < NSLOT; ++j)
            if (j < 12 || t2 < 32) {
                uint32_t k = pk[j];
                int bb = k >> 24, t = (k >> 16) & 1, kp = (k >> 8) & 15, pos = k & 255;
                const float* sp = t ? momF : baseF;
                const float* p  = sp + (b0 + bb) * (CDIM * HW) + coff + kp * 98 + pos;
                float a  = __ldg(p);
                float bq = __ldg(p + 49);
                uint32_t hi = bf16pack(a, bq);
                float h0 = __uint_as_float(hi << 16);
                float h1 = __uint_as_float(hi & 0xFFFF0000u);
                uint32_t d = bb * 2048 + (t ? 1152 + kp * 56 : kp * 72) + pos;
                dbuf[d]                       = hi;
                dbuf[d + (t ? 448u : 576u)]   = bf16pack(a - h0, bq - h1);
                accn[j] = fmaf(a, a, fmaf(bq, bq, accn[j]));
            }
    };

    if (!isMMA) stage(0);

    // ---- main loop ----
    const int bb = wid >> 1;           // batch (MMA warps)
    const int mh = wid & 1;            // m-half: rows [mh*32, mh*32+32)
    float acc[2][7][4];
    #pragma unroll
    for (int tt = 0; tt < 2; ++tt)
        #pragma unroll
        for (int nt = 0; nt < 7; ++nt)
            #pragma unroll
            for (int u = 0; u < 4; ++u) acc[tt][nt][u] = 0.f;

    for (int c = 0; c < NCHUNK; ++c) {
        __syncthreads();
        if (isMMA) {
            const uint32_t* W  = smw + (c & 1) * BUFW + bb * 2048;
            const uint32_t* Bh = W + 1152;
            const int m0 = mh * 32 + gq;
            uint32_t ah[2][4], am[2][4];
            #pragma unroll
            for (int tt = 0; tt < 2; ++tt) {
                int mb = m0 + tt * 16;
                ah[tt][0] = W[tg * 72 + mb];
                ah[tt][1] = W[tg * 72 + mb + 8];
                ah[tt][2] = W[(tg + 4) * 72 + mb];
                ah[tt][3] = W[(tg + 4) * 72 + mb + 8];
                am[tt][0] = W[576 + tg * 72 + mb];
                am[tt][1] = W[576 + tg * 72 + mb + 8];
                am[tt][2] = W[576 + (tg + 4) * 72 + mb];
                am[tt][3] = W[576 + (tg + 4) * 72 + mb + 8];
            }
            #pragma unroll
            for (int nt = 0; nt < 7; ++nt) {
                int o = tg * 56 + nt * 8 + gq;
                uint32_t bh0 = Bh[o],       bh1 = Bh[o + 224];
                uint32_t bm0 = Bh[o + 448], bm1 = Bh[o + 672];
                #pragma unroll
                for (int tt = 0; tt < 2; ++tt) {
                    mma16(acc[tt][nt], ah[tt], bh0, bh1);   // hi * hi
                    mma16(acc[tt][nt], ah[tt], bm0, bm1);   // hi * mid
                    mma16(acc[tt][nt], am[tt], bh0, bh1);   // mid * hi
                }
            }
        } else {
            if (c + 1 < NCHUNK) stage(c + 1);
        }
    }

    // ---- flush norm partials ----
    if (!isMMA) {
        #pragma unroll
        for (int j = 0; j < NSLOT; ++j)
            if (j < 12 || t2 < 32) {
                uint32_t k = pk[j];
                int g = ((k >> 24) * 2) + ((k >> 16) & 1);
                atomicAdd(&sm[SN_OFF + g * 64 + (k & 255)], accn[j]);
            }
    }
    __syncthreads();
    sm[SN_OFF + tid] = rsqrtf(sm[SN_OFF + tid]);
    __syncthreads();

    // ---- epilogue: mask + norms + reduce (MMA warps) ----
    if (isMMA) {
        const float* invP = sm + SN_OFF + (bb * 2 + 0) * 64;  // base norms
        const float* invQ = sm + SN_OFF + (bb * 2 + 1) * 64;  // moment norms
        const float* wm   = sm + WM_OFF;
        float part = 0.f;
        #pragma unroll
        for (int tt = 0; tt < 2; ++tt) {
            int r0 = mh * 32 + tt * 16 + gq;
            int r1 = r0 + 8;
            bool u0 = r0 < HW, u1 = r1 < HW;
            float ip0 = u0 ? invP[r0] : 0.f;
            float ip1 = u1 ? invP[r1] : 0.f;
            #pragma unroll
            for (int nt = 0; nt < 7; ++nt) {
                int q0 = nt * 8 + tg * 2;
                int q1 = q0 + 1;
                if (q0 < HW) {
                    float iq = invQ[q0];
                    if (u0) part = fmaf(acc[tt][nt][0], wm[r0 * HW + q0] * ip0 * iq, part);
                    if (u1) part = fmaf(acc[tt][nt][2], wm[r1 * HW + q0] * ip1 * iq, part);
                }
                if (q1 < HW) {
                    float iq = invQ[q1];
                    if (u0) part = fmaf(acc[tt][nt][1], wm[r0 * HW + q1] * ip0 * iq, part);
                    if (u1) part = fmaf(acc[tt][nt][3], wm[r1 * HW + q1] * ip1 * iq, part);
                }
            }
        }
        #pragma unroll
        for (int o = 16; o; o >>= 1) part += __shfl_xor_sync(0xFFFFFFFFu, part, o);
        if (lane == 0) wsum[wid] = part;
    }
    __syncthreads();
    if (tid < NB)
        out[b0 + tid] = -(wsum[2 * tid] + wsum[2 * tid + 1]) * (1.0f / 2401.0f);
}

extern "C" void kernel_launch(void* const* d_in, const int* in_sizes, int n_in,
                              void* d_out, int out_size) {
    const float* baseF = (const float*)d_in[0];
    const float* momF  = (const float*)d_in[1];
    const int*   baseA = (const int*)d_in[2];
    const int*   momA  = (const int*)d_in[3];
    float* out = (float*)d_out;
    (void)in_sizes; (void)n_in; (void)out_size;

    const int dynBytes = DYN_WORDS * 4;
    cudaFuncSetAttribute(pixpro_ws, cudaFuncAttributeMaxDynamicSharedMemorySize, dynBytes);
    pixpro_ws<<<GRID, NTHR, dynBytes>>>(baseF, momF, baseA, momA, out);
}

// round 8
// speedup vs baseline: 4.1451x; 4.1451x over previous
#include <cuda_runtime.h>
#include <cstdint>

#define HW      49
#define CDIM    256
#define NTHR    256
#define NB      2              // batches per CTA
#define GRID    1024
#define NCHUNK  16             // 16 channels per chunk
#define BUFW    4096           // words per buffer: 2 batches * 2048
#define WM_OFF  8192           // combined mask (float), 2401 (pad 2432)
#define SN_OFF  (WM_OFF + 2432)
#define DYN_WORDS (SN_OFF + 256)
#define NPAIR   1568           // channel-pairs per chunk (2b*2t*8kp*49)

// pack two fp32 -> bf16x2: lower 16 = even channel, upper 16 = odd channel
__device__ __forceinline__ uint32_t bf16pack(float even, float odd) {
    uint32_t r;
    asm("cvt.rn.bf16x2.f32 %0, %1, %2;" : "=r"(r) : "f"(odd), "f"(even));
    return r;
}
__device__ __forceinline__ void mma16(float* d, const uint32_t* a,
                                      uint32_t b0, uint32_t b1) {
    asm("mma.sync.aligned.m16n8k16.row.col.f32.bf16.bf16.f32 "
        "{%0,%1,%2,%3}, {%4,%5,%6,%7}, {%8,%9}, {%0,%1,%2,%3};"
        : "+f"(d[0]), "+f"(d[1]), "+f"(d[2]), "+f"(d[3])
        : "r"(a[0]), "r"(a[1]), "r"(a[2]), "r"(a[3]), "r"(b0), "r"(b1));
}

__global__ __launch_bounds__(NTHR, 2) void pixpro_bf16(
    const float* __restrict__ baseF,   // [B, 256, 49]
    const float* __restrict__ momF,    // [B, 256, 49]
    const int*   __restrict__ baseA,   // [49*49] (p*49+q)
    const int*   __restrict__ momA,    // [49*49]
    float*       __restrict__ out)     // [B]
{
    extern __shared__ float sm[];
    uint32_t* smw = (uint32_t*)sm;
    __shared__ float wsum[8];

    const int tid  = threadIdx.x;
    const int wid  = tid >> 5;
    const int lane = tid & 31;
    const int tg   = lane & 3;
    const int gq   = lane >> 2;
    const int b0   = blockIdx.x * NB;

    // ---- init mask + norm accumulators ----
    for (int i = tid; i < HW * HW; i += NTHR) {
        int p = i / HW, q = i - p * HW;
        sm[WM_OFF + i] = (float)((baseA[i] == 1) + (momA[q * HW + p] == 1));
    }
    for (int i = tid; i < 256; i += NTHR) sm[SN_OFF + i] = 0.f;

    // ---- staging descriptors: off (gmem word, t in sign bit) + dst (smem word) ----
    uint32_t off[7], dst[7];
    float accn[7];
    #pragma unroll
    for (int j = 0; j < 7; ++j) {
        accn[j] = 0.f;
        int e = tid + j * NTHR;
        if (e < NPAIR) {
            int bb = e / 784;
            int r  = e - bb * 784;
            int t  = r / 392;
            int s  = r - t * 392;
            int kp = s / 49;
            int pos = s - kp * 49;
            off[j] = (uint32_t)((b0 + bb) * (CDIM * HW) + kp * 98 + pos)
                   | (t ? 0x80000000u : 0u);
            dst[j] = (uint32_t)(bb * 2048 + (t ? 1152 + kp * 56 : kp * 72) + pos);
        }
    }

    // ---- staging helpers ----
    auto ldg_chunk = [&](float* v0, float* v1, int cc) {
        #pragma unroll
        for (int j = 0; j < 7; ++j)
            if (j < 6 || tid < (NPAIR - 6 * NTHR)) {
                uint32_t o = off[j];
                const float* sp = (o & 0x80000000u) ? momF : baseF;
                const float* p  = sp + (o & 0x7FFFFFFFu) + cc * 784;
                v0[j] = __ldg(p); v1[j] = __ldg(p + 49);
            }
    };
    auto sts_chunk = [&](const float* v0, const float* v1, int bw) {
        uint32_t* dbuf = smw + bw * BUFW;
        #pragma unroll
        for (int j = 0; j < 7; ++j)
            if (j < 6 || tid < (NPAIR - 6 * NTHR)) {
                uint32_t hi = bf16pack(v0[j], v1[j]);
                float h0 = __uint_as_float(hi << 16);
                float h1 = __uint_as_float(hi & 0xFFFF0000u);
                uint32_t mo = (off[j] & 0x80000000u) ? 448u : 576u;
                dbuf[dst[j]]      = hi;
                dbuf[dst[j] + mo] = bf16pack(v0[j] - h0, v1[j] - h1);
                accn[j] = fmaf(v0[j], v0[j], fmaf(v1[j], v1[j], accn[j]));
            }
    };

    // ---- MMA state ----
    const int bb = wid >> 2;
    const int mr = (wid & 3) * 16 + gq;
    float acc[7][4];
    #pragma unroll
    for (int nt = 0; nt < 7; ++nt)
        #pragma unroll
        for (int u = 0; u < 4; ++u) acc[nt][u] = 0.f;

    auto mma_chunk = [&](int bw) {
        const uint32_t* W  = smw + bw * BUFW + bb * 2048;
        const uint32_t* Bh = W + 1152;
        uint32_t ah[4], am[4];
        ah[0] = W[tg * 72 + mr];
        ah[1] = W[tg * 72 + mr + 8];
        ah[2] = W[(tg + 4) * 72 + mr];
        ah[3] = W[(tg + 4) * 72 + mr + 8];
        am[0] = W[576 + tg * 72 + mr];
        am[1] = W[576 + tg * 72 + mr + 8];
        am[2] = W[576 + (tg + 4) * 72 + mr];
        am[3] = W[576 + (tg + 4) * 72 + mr + 8];
        #pragma unroll
        for (int nt = 0; nt < 7; ++nt) {
            int o = tg * 56 + nt * 8 + gq;
            uint32_t bh0 = Bh[o],       bh1 = Bh[o + 224];
            uint32_t bm0 = Bh[o + 448], bm1 = Bh[o + 672];
            mma16(acc[nt], ah, bh0, bh1);   // hi * hi
            mma16(acc[nt], ah, bm0, bm1);   // hi * mid
            mma16(acc[nt], am, bh0, bh1);   // mid * hi
        }
    };

    // ---- prologue: chunk 0 staged directly, chunk 1 prefetched ----
    float va0[7], va1[7], vb0[7], vb1[7];
    ldg_chunk(va0, va1, 0);
    sts_chunk(va0, va1, 0);
    ldg_chunk(vb0, vb1, 1);

    // ---- main loop: two chunks per iteration (prefetch distance 2) ----
    for (int c = 0; c < NCHUNK; c += 2) {
        __syncthreads();                       // buf0 (chunk c) ready
        if (c + 2 < NCHUNK) ldg_chunk(va0, va1, c + 2);
        mma_chunk(0);
        sts_chunk(vb0, vb1, 1);                // chunk c+1 -> buf1

        __syncthreads();                       // buf1 (chunk c+1) ready
        if (c + 3 < NCHUNK) ldg_chunk(vb0, vb1, c + 3);
        mma_chunk(1);
        if (c + 2 < NCHUNK) sts_chunk(va0, va1, 0);   // chunk c+2 -> buf0
    }

    // ---- flush norm partials (recompute group/pos once) ----
    #pragma unroll
    for (int j = 0; j < 7; ++j) {
        int e = tid + j * NTHR;
        if (e < NPAIR) {
            int bbx = e / 784;
            int r   = e - bbx * 784;
            int t   = r / 392;
            int pos = (r - t * 392) % 49;
            atomicAdd(&sm[SN_OFF + (bbx * 2 + t) * 64 + pos], accn[j]);
        }
    }
    __syncthreads();
    sm[SN_OFF + tid] = rsqrtf(sm[SN_OFF + tid]);
    __syncthreads();

    // ---- epilogue: mask + norms + reduce ----
    {
        const float* invP = sm + SN_OFF + (bb * 2 + 0) * 64;  // base norms
        const float* invQ = sm + SN_OFF + (bb * 2 + 1) * 64;  // moment norms
        const float* wm   = sm + WM_OFF;
        const int r0 = mr;
        const int r1 = r0 + 8;
        const int c0 = tg * 2;
        const bool u0 = r0 < HW, u1 = r1 < HW;
        const float ip0 = u0 ? invP[r0] : 0.f;
        const float ip1 = u1 ? invP[r1] : 0.f;
        float part = 0.f;
        #pragma unroll
        for (int nt = 0; nt < 7; ++nt) {
            int q0 = nt * 8 + c0;
            int q1 = q0 + 1;
            if (q0 < HW) {
                float iq = invQ[q0];
                if (u0) part = fmaf(acc[nt][0], wm[r0 * HW + q0] * ip0 * iq, part);
                if (u1) part = fmaf(acc[nt][2], wm[r1 * HW + q0] * ip1 * iq, part);
            }
            if (q1 < HW) {
                float iq = invQ[q1];
                if (u0) part = fmaf(acc[nt][1], wm[r0 * HW + q1] * ip0 * iq, part);
                if (u1) part = fmaf(acc[nt][3], wm[r1 * HW + q1] * ip1 * iq, part);
            }
        }
        #pragma unroll
        for (int o = 16; o; o >>= 1) part += __shfl_xor_sync(0xFFFFFFFFu, part, o);
        if (lane == 0) wsum[wid] = part;
    }
    __syncthreads();
    if (tid < NB) {
        float t = wsum[tid * 4] + wsum[tid * 4 + 1]
                + wsum[tid * 4 + 2] + wsum[tid * 4 + 3];
        out[b0 + tid] = -t * (1.0f / 2401.0f);
    }
}

extern "C" void kernel_launch(void* const* d_in, const int* in_sizes, int n_in,
                              void* d_out, int out_size) {
    const float* baseF = (const float*)d_in[0];
    const float* momF  = (const float*)d_in[1];
    const int*   baseA = (const int*)d_in[2];
    const int*   momA  = (const int*)d_in[3];
    float* out = (float*)d_out;
    (void)in_sizes; (void)n_in; (void)out_size;

    const int dynBytes = DYN_WORDS * 4;
    cudaFuncSetAttribute(pixpro_bf16, cudaFuncAttributeMaxDynamicSharedMemorySize, dynBytes);
    pixpro_bf16<<<GRID, NTHR, dynBytes>>>(baseF, momF, baseA, momA, out);
}